// round 8
// baseline (speedup 1.0000x reference)
#include <cuda_runtime.h>
#include <math.h>

#define Bn 4
#define Cn 7
#define Dn 32
#define Hn 192
#define Wn 192
#define HWn (Hn*Wn)             /* 36864 */
#define DHW (Dn*Hn*Wn)          /* 1179648 */
#define NIDS 16
#define NBINS 32768
#define HALFBINS 16384.0f        /* NBINS/2: err in [0,2] -> bin = err*HALFBINS */

#define INV_W1 (1.0f/191.0f)
#define INV_H1 (1.0f/191.0f)
#define INV_D1 (1.0f/31.0f)

// ---------------- scratch (static device globals; no runtime alloc) ----------
__device__ unsigned long long g_hist[(size_t)Bn*NIDS*NBINS];  // 16 MB
__device__ float g_stats[Bn*NIDS*10];  // cnt, Sw,Sh,Sd, S0,S1,S2, Q0,Q1,Q2
__device__ float g_params[Bn*NIDS*8];  // A,B,C, a,b,c, k, G
__device__ float g_bg[Bn];
__device__ float g_seedl[Bn];
__device__ float g_instb[Bn];
__device__ float g_varb[Bn];
__device__ float g_obj[Bn];

__device__ __forceinline__ float sigmoidf_(float x){ return 1.0f/(1.0f+__expf(-x)); }
__device__ __forceinline__ float fast_tanh(float x){
    x = fminf(x, 15.0f);
    float t = __expf(2.0f*x);
    return __fdividef(t - 1.0f, t + 1.0f);
}

// ---------------- k0: zero scratch ------------------------------------------
__global__ void k_zero(){
    size_t n = (size_t)Bn*NIDS*NBINS;
    for (size_t i = (size_t)blockIdx.x*blockDim.x + threadIdx.x; i < n;
         i += (size_t)gridDim.x*blockDim.x)
        g_hist[i] = 0ULL;
    if (blockIdx.x == 0){
        for (int t = threadIdx.x; t < Bn*NIDS*10; t += blockDim.x) g_stats[t] = 0.f;
        if (threadIdx.x < Bn){
            g_bg[threadIdx.x]=0.f; g_seedl[threadIdx.x]=0.f;
            g_instb[threadIdx.x]=0.f; g_varb[threadIdx.x]=0.f; g_obj[threadIdx.x]=0.f;
        }
    }
}

// ---------------- k1: per-instance stats + bg seed --------------------------
// grid (288, Bn), 256 threads, 16 voxels/thread (288*4096 = DHW)
// Per-warp packed u64 accumulators (warp sees <= 512 voxels -> fields safe):
//   slot0: cnt[0:10) | Sw[10:27) | Sh[27:44) | Sd[44:58)
//   slot1: Sq0[0:32) | Sq1[32:64)    q_i = rint((clamp(s_i)+16)*65536), term<2^21
//   slot2: Sq2[0:32) | Sr0[32:64)    r_i = rint(s_i^2*8192),            term<2^21
//   slot3: Sr1[0:32) | Sr2[32:64)
__global__ void __launch_bounds__(256) k_stats(const float* __restrict__ pred,
                                               const int* __restrict__ inst,
                                               const int* __restrict__ lab){
    const int b    = blockIdx.y;
    const int tid  = threadIdx.x;
    const int warp = tid >> 5, lane = tid & 31;
    __shared__ unsigned long long iacc[8][NIDS][4];  // 4 KB, per-warp replicated
    __shared__ float bgs[8];
    for (int t = tid; t < 8*NIDS*4; t += 256) (&iacc[0][0][0])[t] = 0ULL;
    __syncthreads();

    const float* pb = pred + (size_t)b*Cn*DHW;
    const int base = blockIdx.x * 4096;
    float bg = 0.f;
    #pragma unroll 4
    for (int it = 0; it < 16; ++it){
        int idx = base + it*256 + tid;
        int v = inst[(size_t)b*DHW + idx];
        int l = lab [(size_t)b*DHW + idx];
        float s0 = pb[(size_t)3*DHW + idx];
        float s1 = pb[(size_t)4*DHW + idx];
        float s2 = pb[(size_t)5*DHW + idx];
        float p6 = pb[(size_t)6*DHW + idx];
        if (l == 0){ float s = sigmoidf_(p6); bg = fmaf(s, s, bg); }
        if (v > 0){
            int w = idx % Wn;
            int h = (idx / Wn) % Hn;
            int d = idx / HWn;
            unsigned long long cpk = 1ULL
                | ((unsigned long long)w << 10)
                | ((unsigned long long)h << 27)
                | ((unsigned long long)d << 44);
            s0 = fminf(fmaxf(s0, -15.f), 15.f);
            s1 = fminf(fmaxf(s1, -15.f), 15.f);
            s2 = fminf(fmaxf(s2, -15.f), 15.f);
            unsigned int q0 = (unsigned int)rintf((s0+16.f)*65536.f);
            unsigned int q1 = (unsigned int)rintf((s1+16.f)*65536.f);
            unsigned int q2 = (unsigned int)rintf((s2+16.f)*65536.f);
            unsigned int r0 = (unsigned int)rintf(s0*s0*8192.f);
            unsigned int r1 = (unsigned int)rintf(s1*s1*8192.f);
            unsigned int r2 = (unsigned int)rintf(s2*s2*8192.f);
            unsigned long long* a = iacc[warp][v-1];
            atomicAdd(a+0, cpk);
            atomicAdd(a+1, (unsigned long long)q0 | ((unsigned long long)q1 << 32));
            atomicAdd(a+2, (unsigned long long)q2 | ((unsigned long long)r0 << 32));
            atomicAdd(a+3, (unsigned long long)r1 | ((unsigned long long)r2 << 32));
        }
    }
    for (int o = 16; o; o >>= 1) bg += __shfl_xor_sync(0xffffffffu, bg, o);
    if (lane == 0) bgs[warp] = bg;
    __syncthreads();
    if (tid == 0){
        float s = 0.f;
        for (int w = 0; w < 8; ++w) s += bgs[w];
        atomicAdd(&g_bg[b], s);
    }
    // flush: unpack per warp (unbias with that warp's cnt), sum, global add
    for (int t = tid; t < NIDS; t += 256){
        float cnt=0.f, Sw=0.f, Sh=0.f, Sd=0.f;
        float S0=0.f, S1=0.f, S2=0.f, Q0=0.f, Q1=0.f, Q2=0.f;
        #pragma unroll
        for (int w = 0; w < 8; ++w){
            unsigned long long a0 = iacc[w][t][0];
            float c = (float)(unsigned int)(a0 & 0x3FFULL);
            cnt += c;
            Sw += (float)(unsigned int)((a0 >> 10) & 0x1FFFFULL);
            Sh += (float)(unsigned int)((a0 >> 27) & 0x1FFFFULL);
            Sd += (float)(unsigned int)(a0 >> 44);
            unsigned long long a1 = iacc[w][t][1];
            unsigned long long a2 = iacc[w][t][2];
            unsigned long long a3 = iacc[w][t][3];
            S0 += (float)(unsigned int)a1        * (1.f/65536.f) - 16.f*c;
            S1 += (float)(unsigned int)(a1>>32)  * (1.f/65536.f) - 16.f*c;
            S2 += (float)(unsigned int)a2        * (1.f/65536.f) - 16.f*c;
            Q0 += (float)(unsigned int)(a2>>32)  * (1.f/8192.f);
            Q1 += (float)(unsigned int)a3        * (1.f/8192.f);
            Q2 += (float)(unsigned int)(a3>>32)  * (1.f/8192.f);
        }
        if (cnt > 0.f){
            float* g = &g_stats[((size_t)b*NIDS + t)*10];
            atomicAdd(g+0, cnt); atomicAdd(g+1, Sw); atomicAdd(g+2, Sh); atomicAdd(g+3, Sd);
            atomicAdd(g+4, S0);  atomicAdd(g+5, S1); atomicAdd(g+6, S2);
            atomicAdd(g+7, Q0);  atomicAdd(g+8, Q1); atomicAdd(g+9, Q2);
        }
    }
}

// ---------------- k2: finalize per-instance params --------------------------
__global__ void k_final_stats(){
    int t = threadIdx.x;               // 64 threads
    if (t >= Bn*NIDS) return;
    int b = t / NIDS;
    const float* st = &g_stats[t*10];
    float cnt  = st[0];
    float safe = fmaxf(cnt, 1.f);
    float inv  = 1.f / safe;
    float c0 = st[1]*INV_W1*inv, c1 = st[2]*INV_H1*inv, c2 = st[3]*INV_D1*inv;
    float m0 = st[4]*inv, m1 = st[5]*inv, m2 = st[6]*inv;
    // var = sum_c (Q_c - mu_c*S_c) / (3*safe)
    float var = ((st[7]-m0*st[4]) + (st[8]-m1*st[5]) + (st[9]-m2*st[6])) * (inv*(1.f/3.f));
    float A = expf(10.f*m0), B = expf(10.f*m1), C = expf(10.f*m2);
    float* p = &g_params[t*8];
    p[0] = A;  p[1] = B;  p[2] = C;
    p[3] = -2.f*A*c0; p[4] = -2.f*B*c1; p[5] = -2.f*C*c2;
    p[6] = A*c0*c0 + B*c1*c1 + C*c2*c2;
    p[7] = cnt;
    if (cnt > 0.f){ atomicAdd(&g_varb[b], var); atomicAdd(&g_obj[b], 1.f); }
}

// ---------------- k3: hot pass — dists, histograms, seed loss ---------------
// grid (4608, Bn), 256 threads, 1 voxel/thread
__global__ void __launch_bounds__(256) k_hist(const float* __restrict__ pred,
                                              const int* __restrict__ inst){
    const int b   = blockIdx.y;
    const int tid = threadIdx.x;
    __shared__ float pc[NIDS][7];
    __shared__ float red[8];
    if (tid < NIDS*7){
        int i = tid/7, s = tid%7;
        pc[i][s] = g_params[((size_t)b*NIDS + i)*8 + s];
    }
    __syncthreads();

    const int idx = blockIdx.x*256 + tid;
    const float* pb = pred + (size_t)b*Cn*DHW;
    int w = idx % Wn;
    int h = (idx / Wn) % Hn;
    int d = idx / HWn;
    float e0 = fast_tanh(pb[idx])               + (float)w * INV_W1;
    float e1 = fast_tanh(pb[DHW+idx])           + (float)h * INV_H1;
    float e2 = fast_tanh(pb[2*(size_t)DHW+idx]) + (float)d * INV_D1;
    float seed = sigmoidf_(pb[(size_t)6*DHW + idx]);
    int   v    = inst[(size_t)b*DHW + idx];

    unsigned long long* hb = g_hist + (size_t)b*NIDS*NBINS;
    float sacc = 0.f;
    #pragma unroll
    for (int i = 0; i < NIDS; ++i){
        float q = pc[i][6];
        q = fmaf(fmaf(pc[i][0], e0, pc[i][3]), e0, q);
        q = fmaf(fmaf(pc[i][1], e1, pc[i][4]), e1, q);
        q = fmaf(fmaf(pc[i][2], e2, pc[i][5]), e2, q);
        float dd = __expf(-q);                       // dist, ~(0,1]
        bool  fg = (v == i+1);
        float err = fg ? (2.f - 2.f*dd) : (2.f*dd);
        int bin = (int)(err * HALFBINS);
        bin = min(max(bin, 0), NBINS-1);
        atomicAdd(hb + (size_t)i*NBINS + bin, fg ? (1ULL | (1ULL<<32)) : 1ULL);
        if (fg){ float t2 = seed - dd; sacc = fmaf(t2, t2, sacc); }
    }
    for (int o = 16; o; o >>= 1) sacc += __shfl_xor_sync(0xffffffffu, sacc, o);
    if ((tid & 31) == 0) red[tid >> 5] = sacc;
    __syncthreads();
    if (tid == 0){
        float s = 0.f;
        for (int wq = 0; wq < 8; ++wq) s += red[wq];
        atomicAdd(&g_seedl[b], s);
    }
}

// ---------------- k4: telescoped Lovasz over histogram ----------------------
// 64 blocks (one per (b,iid)), 256 threads, SEG = NBINS/256 bins/thread
__global__ void k_lovasz(){
    const int bi  = blockIdx.x;           // b*NIDS + i
    const int b   = bi / NIDS;
    const int tid = threadIdx.x;
    const float G = g_params[bi*8 + 7];
    if (G < 0.5f) return;                 // uniform across block: safe
    const unsigned long long* h = g_hist + (size_t)bi*NBINS;
    const int SEG = NBINS/256;            // 128

    __shared__ unsigned long long sh[256];
    unsigned int ln = 0, lf = 0;
    const int r0 = tid*SEG;               // rank in descending-err order
    for (int j = 0; j < SEG; ++j){
        unsigned long long hv = h[NBINS-1-(r0+j)];
        ln += (unsigned int)hv;
        lf += (unsigned int)(hv >> 32);
    }
    sh[tid] = (unsigned long long)ln | ((unsigned long long)lf << 32);
    __syncthreads();
    for (int off = 1; off < 256; off <<= 1){
        unsigned long long t = 0;
        if (tid >= off) t = sh[tid-off];
        __syncthreads();
        sh[tid] += t;
        __syncthreads();
    }
    unsigned long long incl = sh[tid];
    unsigned int k = (unsigned int)incl - ln;          // exclusive prefix
    unsigned int f = (unsigned int)(incl >> 32) - lf;

    // J(k,f) = 1 - (G-f)/(G+k-f);  J(0,0) = 0
    float Jprev = 1.f - (G - (float)f) / (G + (float)k - (float)f);
    float contrib = 0.f;
    const float wbin = 2.f / (float)NBINS;
    for (int j = 0; j < SEG; ++j){
        int bin = NBINS-1-(r0+j);
        unsigned long long hv = h[bin];
        unsigned int n = (unsigned int)hv;
        if (n){
            unsigned int fgc = (unsigned int)(hv >> 32);
            k += n; f += fgc;
            float J = 1.f - (G - (float)f) / (G + (float)k - (float)f);
            contrib = fmaf(((float)bin + 0.5f)*wbin, J - Jprev, contrib);
            Jprev = J;
        }
    }
    __shared__ float rf[8];
    for (int o = 16; o; o >>= 1) contrib += __shfl_xor_sync(0xffffffffu, contrib, o);
    if ((tid & 31) == 0) rf[tid >> 5] = contrib;
    __syncthreads();
    if (tid == 0){
        float s = 0.f;
        for (int wq = 0; wq < 8; ++wq) s += rf[wq];
        atomicAdd(&g_instb[b], s);
    }
}

// ---------------- k5: assemble outputs --------------------------------------
__global__ void k_finalize(float* __restrict__ out){
    float li = 0.f, lv = 0.f, ls = 0.f;
    for (int b = 0; b < Bn; ++b){
        float denom = fmaxf(g_obj[b], 1.f);
        li += g_instb[b] / denom;
        lv += g_varb[b]  / denom;
        ls += (g_seedl[b] + g_bg[b]) * (1.f/(float)DHW);
    }
    li *= (1.0f / (float)Bn);    // W_INST = 1
    lv *= (10.0f / (float)Bn);   // W_VAR  = 10
    ls *= (1.0f / (float)Bn);    // W_SEED = 1
    out[0] = li; out[1] = lv; out[2] = ls; out[3] = li + lv + ls;
}

// ---------------- launch ----------------------------------------------------
extern "C" void kernel_launch(void* const* d_in, const int* in_sizes, int n_in,
                              void* d_out, int out_size){
    const float* pred = (const float*)d_in[0];
    const int*   inst = (const int*)  d_in[1];
    const int*   lab  = (const int*)  d_in[2];
    // d_in[3] = center_images (unused by the reference)
    // d_in[4] = xyzm (recomputed analytically on device)
    float* out = (float*)d_out;

    k_zero       <<<4096, 256>>>();
    k_stats      <<<dim3(288, Bn), 256>>>(pred, inst, lab);
    k_final_stats<<<1, 64>>>();
    k_hist       <<<dim3(4608, Bn), 256>>>(pred, inst);
    k_lovasz     <<<Bn*NIDS, 256>>>();
    k_finalize   <<<1, 1>>>(out);
}